// round 7
// baseline (speedup 1.0000x reference)
#include <cuda_runtime.h>

// Problem shape (fixed by the dataset)
#define BB 16
#define NN 8192
#define FF 256
#define ROW4 64                      // float4s per row (FF/4)
#define RPB 64                       // rows per block-slab
#define IT  ((RPB * ROW4) / 256)     // 16 unrolled iterations per slab
#define EPS 1e-3f

// Scratch (allocation-free rule: __device__ globals)
__device__ float g_sum[FF];
__device__ float g_sumsq[FF];
__device__ float g_scale[FF];
__device__ float g_shift[FF];

// ---------------- kernel 0: zero accumulators ----------------
__global__ void mbn_zero_kernel() {
    int t = threadIdx.x;          // 256 threads
    g_sum[t]   = 0.0f;
    g_sumsq[t] = 0.0f;
}

// ---------------- kernel 1: masked sum / sumsq (slab-structured) ----------------
// Block (bx, b) handles rows [bx*RPB, bx*RPB+RPB) of batch b.
// Thread t always touches feature group t&63 (indices i*256+t keep (..)&63 == t&63).
__global__ void mbn_stats_kernel(const float4* __restrict__ x,
                                 const int* __restrict__ nv) {
    int b   = blockIdx.y;
    int nvb = __ldg(&nv[b]);
    int r0  = blockIdx.x * RPB;
    if (r0 >= nvb) return;                         // fully padded slab: no work

    int tid = threadIdx.x;
    const float4* base = x + ((size_t)b * NN + r0) * ROW4;

    float s0 = 0.f, s1 = 0.f, s2 = 0.f, s3 = 0.f;
    float q0 = 0.f, q1 = 0.f, q2 = 0.f, q3 = 0.f;

    if (r0 + RPB <= nvb) {
        // Fully valid: unconditional, fully unrolled -> batched LDG.128s
        #pragma unroll
        for (int i = 0; i < IT; i++) {
            float4 v = base[i * 256 + tid];
            s0 += v.x; s1 += v.y; s2 += v.z; s3 += v.w;
            q0 += v.x * v.x; q1 += v.y * v.y;
            q2 += v.z * v.z; q3 += v.w * v.w;
        }
    } else {
        // Boundary slab (one per batch)
        int total = (nvb - r0) * ROW4;
        for (int i = tid; i < total; i += 256) {
            float4 v = base[i];
            s0 += v.x; s1 += v.y; s2 += v.z; s3 += v.w;
            q0 += v.x * v.x; q1 += v.y * v.y;
            q2 += v.z * v.z; q3 += v.w * v.w;
        }
    }

    // Block reduction: threads {t, t+64, t+128, t+192} share a feature group.
    __shared__ float red[256 * 4];
    red[tid * 4 + 0] = s0; red[tid * 4 + 1] = s1;
    red[tid * 4 + 2] = s2; red[tid * 4 + 3] = s3;
    __syncthreads();
    if (tid < 64) {
        #pragma unroll
        for (int j = 0; j < 4; j++) {
            float t = red[tid * 4 + j] + red[(tid + 64) * 4 + j] +
                      red[(tid + 128) * 4 + j] + red[(tid + 192) * 4 + j];
            atomicAdd(&g_sum[tid * 4 + j], t);
        }
    }
    __syncthreads();
    red[tid * 4 + 0] = q0; red[tid * 4 + 1] = q1;
    red[tid * 4 + 2] = q2; red[tid * 4 + 3] = q3;
    __syncthreads();
    if (tid < 64) {
        #pragma unroll
        for (int j = 0; j < 4; j++) {
            float t = red[tid * 4 + j] + red[(tid + 64) * 4 + j] +
                      red[(tid + 128) * 4 + j] + red[(tid + 192) * 4 + j];
            atomicAdd(&g_sumsq[tid * 4 + j], t);
        }
    }
}

// ---------------- kernel 2: finalize scale/shift ----------------
__global__ void mbn_finalize_kernel(const int* __restrict__ nv,
                                    const float* __restrict__ gamma,
                                    const float* __restrict__ beta) {
    __shared__ float s_cnt;
    if (threadIdx.x == 0) {
        int c = 0;
        #pragma unroll
        for (int i = 0; i < BB; i++) c += nv[i];
        s_cnt = fmaxf((float)c, 1.0f);
    }
    __syncthreads();
    int f = threadIdx.x;                      // 256 threads
    float cnt  = s_cnt;
    float mean = g_sum[f] / cnt;
    float var  = g_sumsq[f] / cnt - mean * mean;
    float inv  = rsqrtf(var + EPS);
    float sc   = inv * gamma[f];
    g_scale[f] = sc;
    g_shift[f] = beta[f] - mean * sc;
}

// ---------------- kernel 3: normalize + zero padding (slab-structured) ----------------
__global__ void mbn_norm_kernel(const float4* __restrict__ x,
                                const int* __restrict__ nv,
                                float4* __restrict__ out) {
    int b   = blockIdx.y;
    int nvb = __ldg(&nv[b]);
    int r0  = blockIdx.x * RPB;
    int tid = threadIdx.x;

    size_t off = ((size_t)b * NN + r0) * ROW4;
    const float4* in = x + off;
    float4*       o  = out + off;

    if (r0 >= nvb) {
        // Fully padded slab: pure zero stores, no loads at all.
        float4 z = make_float4(0.f, 0.f, 0.f, 0.f);
        #pragma unroll
        for (int i = 0; i < IT; i++) o[i * 256 + tid] = z;
        return;
    }

    // Register-resident scale/shift: this thread only ever touches 4 features.
    int fg = (tid & 63) * 4;
    float sc0 = g_scale[fg + 0], sc1 = g_scale[fg + 1];
    float sc2 = g_scale[fg + 2], sc3 = g_scale[fg + 3];
    float sh0 = g_shift[fg + 0], sh1 = g_shift[fg + 1];
    float sh2 = g_shift[fg + 2], sh3 = g_shift[fg + 3];

    if (r0 + RPB <= nvb) {
        // Fully valid: unconditional unrolled load -> fma -> store
        #pragma unroll
        for (int i = 0; i < IT; i++) {
            float4 v = in[i * 256 + tid];
            float4 r;
            r.x = fmaf(v.x, sc0, sh0);
            r.y = fmaf(v.y, sc1, sh1);
            r.z = fmaf(v.z, sc2, sh2);
            r.w = fmaf(v.w, sc3, sh3);
            o[i * 256 + tid] = r;
        }
    } else {
        // Boundary slab (one per batch)
        int total = (nvb - r0) * ROW4;
        #pragma unroll 4
        for (int i = tid; i < RPB * ROW4; i += 256) {
            float4 r = make_float4(0.f, 0.f, 0.f, 0.f);
            if (i < total) {
                float4 v = in[i];
                r.x = fmaf(v.x, sc0, sh0);
                r.y = fmaf(v.y, sc1, sh1);
                r.z = fmaf(v.z, sc2, sh2);
                r.w = fmaf(v.w, sc3, sh3);
            }
            o[i] = r;
        }
    }
}

extern "C" void kernel_launch(void* const* d_in, const int* in_sizes, int n_in,
                              void* d_out, int out_size) {
    const float4* x     = (const float4*)d_in[0];   // voxel_features [16,8192,256]
    const int*    nv    = (const int*)d_in[1];      // num_valid_voxels [16]
    const float*  gamma = (const float*)d_in[2];    // [256]
    const float*  beta  = (const float*)d_in[3];    // [256]
    float4*       out   = (float4*)d_out;

    const int threads = 256;
    dim3 grid_slab(NN / RPB, BB);   // (128, 16) = 2048 blocks

    mbn_zero_kernel<<<1, threads>>>();
    mbn_stats_kernel<<<grid_slab, threads>>>(x, nv);
    mbn_finalize_kernel<<<1, threads>>>(nv, gamma, beta);
    mbn_norm_kernel<<<grid_slab, threads>>>(x, nv, out);
}

// round 8
// speedup vs baseline: 1.1164x; 1.1164x over previous
#include <cuda_runtime.h>

// Problem shape (fixed by the dataset)
#define BB 16
#define NN 8192
#define FF 256
#define ROW4 64                       // float4s per row (FF/4)
#define NROWS (BB * NN)               // 131072
#define SLAB_ROWS 4
#define NSLAB (NROWS / SLAB_ROWS)     // 32768 warp-slabs; 8192 % 4 == 0 -> no batch crossing
#define EPS 1e-3f

// Scratch (allocation-free rule: __device__ globals). 16B-aligned for float4 views.
__device__ __align__(16) float g_sum[FF];
__device__ __align__(16) float g_sumsq[FF];
__device__ __align__(16) float g_scale[FF];
__device__ __align__(16) float g_shift[FF];

// ---------------- kernel 0: zero accumulators ----------------
__global__ void mbn_zero_kernel() {
    int t = threadIdx.x;          // 256 threads
    g_sum[t]   = 0.0f;
    g_sumsq[t] = 0.0f;
}

// ---------------- kernel 1: masked sum / sumsq (warp-slab, grid-stride) ----------------
// A warp owns 4-row slabs; lane l accumulates float4 cols {l, l+32} of each row,
// i.e. features {4l..4l+3} and {128+4l..128+4l+3}. Valid slabs -> 8 unconditional
// batched LDG.128 (MLP 8); invalid slabs skip inside the loop (balanced).
__global__ void mbn_stats_kernel(const float4* __restrict__ x,
                                 const int* __restrict__ nv) {
    __shared__ int s_nv[BB];
    if (threadIdx.x < BB) s_nv[threadIdx.x] = nv[threadIdx.x];
    __syncthreads();

    int tid  = threadIdx.x;
    int lane = tid & 31;
    int gw   = blockIdx.x * (blockDim.x >> 5) + (tid >> 5);
    int W    = gridDim.x * (blockDim.x >> 5);

    float sA0 = 0.f, sA1 = 0.f, sA2 = 0.f, sA3 = 0.f;
    float sB0 = 0.f, sB1 = 0.f, sB2 = 0.f, sB3 = 0.f;
    float qA0 = 0.f, qA1 = 0.f, qA2 = 0.f, qA3 = 0.f;
    float qB0 = 0.f, qB1 = 0.f, qB2 = 0.f, qB3 = 0.f;

    for (int s = gw; s < NSLAB; s += W) {
        int row0 = s << 2;                 // * SLAB_ROWS
        int n    = row0 & (NN - 1);
        int b    = row0 >> 13;
        int nvb  = s_nv[b];
        if (n + SLAB_ROWS <= nvb) {
            const float4* p = x + (size_t)row0 * ROW4;
            #pragma unroll
            for (int r = 0; r < SLAB_ROWS; r++) {
                float4 va = p[r * ROW4 + lane];
                float4 vb = p[r * ROW4 + lane + 32];
                sA0 += va.x; sA1 += va.y; sA2 += va.z; sA3 += va.w;
                qA0 += va.x * va.x; qA1 += va.y * va.y;
                qA2 += va.z * va.z; qA3 += va.w * va.w;
                sB0 += vb.x; sB1 += vb.y; sB2 += vb.z; sB3 += vb.w;
                qB0 += vb.x * vb.x; qB1 += vb.y * vb.y;
                qB2 += vb.z * vb.z; qB3 += vb.w * vb.w;
            }
        } else if (n < nvb) {
            // Boundary slab: at most one per batch (<=16 total)
            int cnt = nvb - n;             // 1..3
            const float4* p = x + (size_t)row0 * ROW4;
            for (int r = 0; r < cnt; r++) {
                float4 va = p[r * ROW4 + lane];
                float4 vb = p[r * ROW4 + lane + 32];
                sA0 += va.x; sA1 += va.y; sA2 += va.z; sA3 += va.w;
                qA0 += va.x * va.x; qA1 += va.y * va.y;
                qA2 += va.z * va.z; qA3 += va.w * va.w;
                sB0 += vb.x; sB1 += vb.y; sB2 += vb.z; sB3 += vb.w;
                qB0 += vb.x * vb.x; qB1 += vb.y * vb.y;
                qB2 += vb.z * vb.z; qB3 += vb.w * vb.w;
            }
        }
        // else fully padded: skip
    }

    // Block reduction: threads with equal lane (8 warps) share feature groups.
    __shared__ float red[256 * 4];
    #define RED_ROUND(v0, v1, v2, v3, dst, foff)                               \
        red[tid * 4 + 0] = v0; red[tid * 4 + 1] = v1;                          \
        red[tid * 4 + 2] = v2; red[tid * 4 + 3] = v3;                          \
        __syncthreads();                                                       \
        if (tid < 32) {                                                        \
            _Pragma("unroll")                                                  \
            for (int j = 0; j < 4; j++) {                                      \
                float t = 0.f;                                                 \
                _Pragma("unroll")                                              \
                for (int w = 0; w < 8; w++) t += red[(w * 32 + tid) * 4 + j];  \
                atomicAdd(&dst[(foff) + tid * 4 + j], t);                      \
            }                                                                  \
        }                                                                      \
        __syncthreads();

    RED_ROUND(sA0, sA1, sA2, sA3, g_sum,   0)
    RED_ROUND(sB0, sB1, sB2, sB3, g_sum,   128)
    RED_ROUND(qA0, qA1, qA2, qA3, g_sumsq, 0)
    RED_ROUND(qB0, qB1, qB2, qB3, g_sumsq, 128)
    #undef RED_ROUND
}

// ---------------- kernel 2: finalize scale/shift ----------------
__global__ void mbn_finalize_kernel(const int* __restrict__ nv,
                                    const float* __restrict__ gamma,
                                    const float* __restrict__ beta) {
    __shared__ float s_cnt;
    if (threadIdx.x == 0) {
        int c = 0;
        #pragma unroll
        for (int i = 0; i < BB; i++) c += nv[i];
        s_cnt = fmaxf((float)c, 1.0f);
    }
    __syncthreads();
    int f = threadIdx.x;                      // 256 threads
    float cnt  = s_cnt;
    float mean = g_sum[f] / cnt;
    float var  = g_sumsq[f] / cnt - mean * mean;
    float inv  = rsqrtf(var + EPS);
    float sc   = inv * gamma[f];
    g_scale[f] = sc;
    g_shift[f] = beta[f] - mean * sc;
}

// ---------------- kernel 3: normalize + zero padding (warp-slab, grid-stride) ----------------
__global__ void mbn_norm_kernel(const float4* __restrict__ x,
                                const int* __restrict__ nv,
                                float4* __restrict__ out) {
    __shared__ int s_nv[BB];
    if (threadIdx.x < BB) s_nv[threadIdx.x] = nv[threadIdx.x];
    __syncthreads();

    int tid  = threadIdx.x;
    int lane = tid & 31;
    int gw   = blockIdx.x * (blockDim.x >> 5) + (tid >> 5);
    int W    = gridDim.x * (blockDim.x >> 5);

    // Register-resident scale/shift: lane l only ever touches cols l and l+32.
    const float4* sc4 = (const float4*)g_scale;
    const float4* sh4 = (const float4*)g_shift;
    float4 scA = sc4[lane], scB = sc4[lane + 32];
    float4 shA = sh4[lane], shB = sh4[lane + 32];
    const float4 z4 = make_float4(0.f, 0.f, 0.f, 0.f);

    for (int s = gw; s < NSLAB; s += W) {
        int row0 = s << 2;
        int n    = row0 & (NN - 1);
        int b    = row0 >> 13;
        int nvb  = s_nv[b];
        size_t off = (size_t)row0 * ROW4;
        float4* po = out + off;

        if (n + SLAB_ROWS <= nvb) {
            const float4* p = x + off;
            #pragma unroll
            for (int r = 0; r < SLAB_ROWS; r++) {
                float4 va = p[r * ROW4 + lane];
                float4 vb = p[r * ROW4 + lane + 32];
                float4 ra, rb;
                ra.x = fmaf(va.x, scA.x, shA.x);
                ra.y = fmaf(va.y, scA.y, shA.y);
                ra.z = fmaf(va.z, scA.z, shA.z);
                ra.w = fmaf(va.w, scA.w, shA.w);
                rb.x = fmaf(vb.x, scB.x, shB.x);
                rb.y = fmaf(vb.y, scB.y, shB.y);
                rb.z = fmaf(vb.z, scB.z, shB.z);
                rb.w = fmaf(vb.w, scB.w, shB.w);
                po[r * ROW4 + lane]      = ra;
                po[r * ROW4 + lane + 32] = rb;
            }
        } else if (n >= nvb) {
            // Fully padded slab: store-only zero fill, no reads.
            #pragma unroll
            for (int r = 0; r < SLAB_ROWS; r++) {
                po[r * ROW4 + lane]      = z4;
                po[r * ROW4 + lane + 32] = z4;
            }
        } else {
            // Boundary slab (<=16 total)
            int cnt = nvb - n;             // 1..3
            const float4* p = x + off;
            #pragma unroll
            for (int r = 0; r < SLAB_ROWS; r++) {
                float4 ra = z4, rb = z4;
                if (r < cnt) {
                    float4 va = p[r * ROW4 + lane];
                    float4 vb = p[r * ROW4 + lane + 32];
                    ra.x = fmaf(va.x, scA.x, shA.x);
                    ra.y = fmaf(va.y, scA.y, shA.y);
                    ra.z = fmaf(va.z, scA.z, shA.z);
                    ra.w = fmaf(va.w, scA.w, shA.w);
                    rb.x = fmaf(vb.x, scB.x, shB.x);
                    rb.y = fmaf(vb.y, scB.y, shB.y);
                    rb.z = fmaf(vb.z, scB.z, shB.z);
                    rb.w = fmaf(vb.w, scB.w, shB.w);
                }
                po[r * ROW4 + lane]      = ra;
                po[r * ROW4 + lane + 32] = rb;
            }
        }
    }
}

extern "C" void kernel_launch(void* const* d_in, const int* in_sizes, int n_in,
                              void* d_out, int out_size) {
    const float4* x     = (const float4*)d_in[0];   // voxel_features [16,8192,256]
    const int*    nv    = (const int*)d_in[1];      // num_valid_voxels [16]
    const float*  gamma = (const float*)d_in[2];    // [256]
    const float*  beta  = (const float*)d_in[3];    // [256]
    float4*       out   = (float4*)d_out;

    const int threads = 256;
    const int grid    = 148 * 8;    // persistent-ish grid-stride, full residency

    mbn_zero_kernel<<<1, threads>>>();
    mbn_stats_kernel<<<grid, threads>>>(x, nv);
    mbn_finalize_kernel<<<1, threads>>>(nv, gamma, beta);
    mbn_norm_kernel<<<grid, threads>>>(x, nv, out);
}

// round 9
// speedup vs baseline: 1.4995x; 1.3431x over previous
#include <cuda_runtime.h>

// Problem shape (fixed by the dataset)
#define BB 16
#define NN 8192
#define FF 256
#define ROW4 64                       // float4s per row (FF/4)
#define NROWS (BB * NN)               // 131072
#define SLAB_ROWS 4
#define NSLAB (NROWS / SLAB_ROWS)     // 32768 warp-slabs; 8192 % 4 == 0 -> no batch crossing
#define NBLK 148                      // one stats block per SM
#define EPS 1e-3f

// Scratch (allocation-free rule: __device__ globals). 16B-aligned for float4 views.
// g_part[blk][0..255] = per-block sum partials, [256..511] = sumsq partials.
__device__ __align__(16) float g_part[NBLK * 2 * FF];
__device__ __align__(16) float g_scale[FF];
__device__ __align__(16) float g_shift[FF];

// ---------------- kernel 1: masked sum / sumsq (warp-slab, no atomics) ----------------
// A warp owns 4-row slabs; lane l accumulates float4 cols {l, l+32} of each row,
// i.e. features {4l..4l+3} and {128+4l..128+4l+3}. Valid slabs -> 8 unconditional
// batched LDG.128 (MLP 8); padded slabs skip inside the loop (balanced).
// Per-block result is STORED to g_part (no atomic contention).
__global__ void mbn_stats_kernel(const float4* __restrict__ x,
                                 const int* __restrict__ nv) {
    __shared__ int s_nv[BB];
    if (threadIdx.x < BB) s_nv[threadIdx.x] = nv[threadIdx.x];
    __syncthreads();

    int tid  = threadIdx.x;
    int lane = tid & 31;
    int gw   = blockIdx.x * (blockDim.x >> 5) + (tid >> 5);
    int W    = gridDim.x * (blockDim.x >> 5);

    float sA0 = 0.f, sA1 = 0.f, sA2 = 0.f, sA3 = 0.f;
    float sB0 = 0.f, sB1 = 0.f, sB2 = 0.f, sB3 = 0.f;
    float qA0 = 0.f, qA1 = 0.f, qA2 = 0.f, qA3 = 0.f;
    float qB0 = 0.f, qB1 = 0.f, qB2 = 0.f, qB3 = 0.f;

    for (int s = gw; s < NSLAB; s += W) {
        int row0 = s << 2;                 // * SLAB_ROWS
        int n    = row0 & (NN - 1);
        int b    = row0 >> 13;
        int nvb  = s_nv[b];
        if (n + SLAB_ROWS <= nvb) {
            const float4* p = x + (size_t)row0 * ROW4;
            #pragma unroll
            for (int r = 0; r < SLAB_ROWS; r++) {
                float4 va = p[r * ROW4 + lane];
                float4 vb = p[r * ROW4 + lane + 32];
                sA0 += va.x; sA1 += va.y; sA2 += va.z; sA3 += va.w;
                qA0 += va.x * va.x; qA1 += va.y * va.y;
                qA2 += va.z * va.z; qA3 += va.w * va.w;
                sB0 += vb.x; sB1 += vb.y; sB2 += vb.z; sB3 += vb.w;
                qB0 += vb.x * vb.x; qB1 += vb.y * vb.y;
                qB2 += vb.z * vb.z; qB3 += vb.w * vb.w;
            }
        } else if (n < nvb) {
            // Boundary slab: at most one per batch (<=16 total)
            int cnt = nvb - n;             // 1..3
            const float4* p = x + (size_t)row0 * ROW4;
            for (int r = 0; r < cnt; r++) {
                float4 va = p[r * ROW4 + lane];
                float4 vb = p[r * ROW4 + lane + 32];
                sA0 += va.x; sA1 += va.y; sA2 += va.z; sA3 += va.w;
                qA0 += va.x * va.x; qA1 += va.y * va.y;
                qA2 += va.z * va.z; qA3 += va.w * va.w;
                sB0 += vb.x; sB1 += vb.y; sB2 += vb.z; sB3 += vb.w;
                qB0 += vb.x * vb.x; qB1 += vb.y * vb.y;
                qB2 += vb.z * vb.z; qB3 += vb.w * vb.w;
            }
        }
        // else fully padded: skip
    }

    // Block reduction: threads with equal lane (8 warps) share feature groups.
    // Then STORE partials (no atomics).
    __shared__ float red[256 * 4];
    float* myPart = &g_part[(size_t)blockIdx.x * (2 * FF)];
    #define RED_ROUND(v0, v1, v2, v3, foff)                                    \
        red[tid * 4 + 0] = v0; red[tid * 4 + 1] = v1;                          \
        red[tid * 4 + 2] = v2; red[tid * 4 + 3] = v3;                          \
        __syncthreads();                                                       \
        if (tid < 32) {                                                        \
            _Pragma("unroll")                                                  \
            for (int j = 0; j < 4; j++) {                                      \
                float t = 0.f;                                                 \
                _Pragma("unroll")                                              \
                for (int w = 0; w < 8; w++) t += red[(w * 32 + tid) * 4 + j];  \
                myPart[(foff) + tid * 4 + j] = t;                              \
            }                                                                  \
        }                                                                      \
        __syncthreads();

    RED_ROUND(sA0, sA1, sA2, sA3, 0)        // sum, features 0..127
    RED_ROUND(sB0, sB1, sB2, sB3, 128)      // sum, features 128..255
    RED_ROUND(qA0, qA1, qA2, qA3, 256)      // sumsq, features 0..127
    RED_ROUND(qB0, qB1, qB2, qB3, 256 + 128)// sumsq, features 128..255
    #undef RED_ROUND
}

// ---------------- kernel 2: reduce partials + finalize scale/shift ----------------
__global__ void mbn_finalize_kernel(const int* __restrict__ nv,
                                    const float* __restrict__ gamma,
                                    const float* __restrict__ beta) {
    __shared__ float s_cnt;
    if (threadIdx.x == 0) {
        int c = 0;
        #pragma unroll
        for (int i = 0; i < BB; i++) c += nv[i];
        s_cnt = fmaxf((float)c, 1.0f);
    }
    int f = threadIdx.x;                      // 256 threads, coalesced over partials
    float sum = 0.f, sumsq = 0.f;
    #pragma unroll 4
    for (int blk = 0; blk < NBLK; blk++) {
        const float* p = &g_part[(size_t)blk * (2 * FF)];
        sum   += p[f];
        sumsq += p[FF + f];
    }
    __syncthreads();
    float cnt  = s_cnt;
    float mean = sum / cnt;
    float var  = sumsq / cnt - mean * mean;
    float inv  = rsqrtf(var + EPS);
    float sc   = inv * gamma[f];
    g_scale[f] = sc;
    g_shift[f] = beta[f] - mean * sc;
}

// ---------------- kernel 3: normalize + zero padding (warp-slab, grid-stride) ----------------
// Unchanged from R8 (measured 29.3us, at the HBM wall).
__global__ void mbn_norm_kernel(const float4* __restrict__ x,
                                const int* __restrict__ nv,
                                float4* __restrict__ out) {
    __shared__ int s_nv[BB];
    if (threadIdx.x < BB) s_nv[threadIdx.x] = nv[threadIdx.x];
    __syncthreads();

    int tid  = threadIdx.x;
    int lane = tid & 31;
    int gw   = blockIdx.x * (blockDim.x >> 5) + (tid >> 5);
    int W    = gridDim.x * (blockDim.x >> 5);

    // Register-resident scale/shift: lane l only ever touches cols l and l+32.
    const float4* sc4 = (const float4*)g_scale;
    const float4* sh4 = (const float4*)g_shift;
    float4 scA = sc4[lane], scB = sc4[lane + 32];
    float4 shA = sh4[lane], shB = sh4[lane + 32];
    const float4 z4 = make_float4(0.f, 0.f, 0.f, 0.f);

    for (int s = gw; s < NSLAB; s += W) {
        int row0 = s << 2;
        int n    = row0 & (NN - 1);
        int b    = row0 >> 13;
        int nvb  = s_nv[b];
        size_t off = (size_t)row0 * ROW4;
        float4* po = out + off;

        if (n + SLAB_ROWS <= nvb) {
            const float4* p = x + off;
            #pragma unroll
            for (int r = 0; r < SLAB_ROWS; r++) {
                float4 va = p[r * ROW4 + lane];
                float4 vb = p[r * ROW4 + lane + 32];
                float4 ra, rb;
                ra.x = fmaf(va.x, scA.x, shA.x);
                ra.y = fmaf(va.y, scA.y, shA.y);
                ra.z = fmaf(va.z, scA.z, shA.z);
                ra.w = fmaf(va.w, scA.w, shA.w);
                rb.x = fmaf(vb.x, scB.x, shB.x);
                rb.y = fmaf(vb.y, scB.y, shB.y);
                rb.z = fmaf(vb.z, scB.z, shB.z);
                rb.w = fmaf(vb.w, scB.w, shB.w);
                po[r * ROW4 + lane]      = ra;
                po[r * ROW4 + lane + 32] = rb;
            }
        } else if (n >= nvb) {
            // Fully padded slab: store-only zero fill, no reads.
            #pragma unroll
            for (int r = 0; r < SLAB_ROWS; r++) {
                po[r * ROW4 + lane]      = z4;
                po[r * ROW4 + lane + 32] = z4;
            }
        } else {
            // Boundary slab (<=16 total)
            int cnt = nvb - n;             // 1..3
            const float4* p = x + off;
            #pragma unroll
            for (int r = 0; r < SLAB_ROWS; r++) {
                float4 ra = z4, rb = z4;
                if (r < cnt) {
                    float4 va = p[r * ROW4 + lane];
                    float4 vb = p[r * ROW4 + lane + 32];
                    ra.x = fmaf(va.x, scA.x, shA.x);
                    ra.y = fmaf(va.y, scA.y, shA.y);
                    ra.z = fmaf(va.z, scA.z, shA.z);
                    ra.w = fmaf(va.w, scA.w, shA.w);
                    rb.x = fmaf(vb.x, scB.x, shB.x);
                    rb.y = fmaf(vb.y, scB.y, shB.y);
                    rb.z = fmaf(vb.z, scB.z, shB.z);
                    rb.w = fmaf(vb.w, scB.w, shB.w);
                }
                po[r * ROW4 + lane]      = ra;
                po[r * ROW4 + lane + 32] = rb;
            }
        }
    }
}

extern "C" void kernel_launch(void* const* d_in, const int* in_sizes, int n_in,
                              void* d_out, int out_size) {
    const float4* x     = (const float4*)d_in[0];   // voxel_features [16,8192,256]
    const int*    nv    = (const int*)d_in[1];      // num_valid_voxels [16]
    const float*  gamma = (const float*)d_in[2];    // [256]
    const float*  beta  = (const float*)d_in[3];    // [256]
    float4*       out   = (float4*)d_out;

    const int threads = 256;

    mbn_stats_kernel<<<NBLK, threads>>>(x, nv);          // 148 blocks, no atomics
    mbn_finalize_kernel<<<1, threads>>>(nv, gamma, beta);
    mbn_norm_kernel<<<148 * 8, threads>>>(x, nv, out);
}

// round 11
// speedup vs baseline: 1.6526x; 1.1021x over previous
#include <cuda_runtime.h>

// Problem shape (fixed by the dataset)
#define BB 16
#define NN 8192
#define FF 256
#define ROW4 64                       // float4s per row (FF/4)
#define NROWS (BB * NN)               // 131072
#define SLAB_ROWS 4
#define NSLAB (NROWS / SLAB_ROWS)     // 32768 warp-slabs; 8192 % 4 == 0 -> no batch crossing
#define NBLK 148                      // one stats block per SM
#define STATS_T 1024                  // 32 warps per stats block
#define EPS 1e-3f

// Scratch (allocation-free rule: __device__ globals). 16B-aligned for float4 views.
// g_part[blk][0..255] = per-block sum partials, [256..511] = sumsq partials.
__device__ __align__(16) float g_part[NBLK * 2 * FF];
__device__ __align__(16) float g_scale[FF];
__device__ __align__(16) float g_shift[FF];

// ---------------- kernel 1: masked sum / sumsq (warp-slab, 32 warps/SM, no atomics) ----------------
// A warp owns 4-row slabs; lane l accumulates float4 cols {l, l+32} of each row,
// i.e. features {4l..4l+3} and {128+4l..128+4l+3}. Valid slabs -> 8 unconditional
// batched LDG.128 (MLP 8); padded slabs skip inside the loop (balanced).
__global__ __launch_bounds__(STATS_T, 1)
void mbn_stats_kernel(const float4* __restrict__ x,
                      const int* __restrict__ nv) {
    __shared__ int s_nv[BB];
    if (threadIdx.x < BB) s_nv[threadIdx.x] = nv[threadIdx.x];
    __syncthreads();

    int tid  = threadIdx.x;
    int lane = tid & 31;
    int gw   = blockIdx.x * (STATS_T >> 5) + (tid >> 5);
    const int W = NBLK * (STATS_T >> 5);       // 4736 warps chip-wide

    float sA0 = 0.f, sA1 = 0.f, sA2 = 0.f, sA3 = 0.f;
    float sB0 = 0.f, sB1 = 0.f, sB2 = 0.f, sB3 = 0.f;
    float qA0 = 0.f, qA1 = 0.f, qA2 = 0.f, qA3 = 0.f;
    float qB0 = 0.f, qB1 = 0.f, qB2 = 0.f, qB3 = 0.f;

    for (int s = gw; s < NSLAB; s += W) {
        int row0 = s << 2;                 // * SLAB_ROWS
        int n    = row0 & (NN - 1);
        int b    = row0 >> 13;
        int nvb  = s_nv[b];
        if (n + SLAB_ROWS <= nvb) {
            const float4* p = x + (size_t)row0 * ROW4;
            #pragma unroll
            for (int r = 0; r < SLAB_ROWS; r++) {
                float4 va = p[r * ROW4 + lane];
                float4 vb = p[r * ROW4 + lane + 32];
                sA0 += va.x; sA1 += va.y; sA2 += va.z; sA3 += va.w;
                qA0 += va.x * va.x; qA1 += va.y * va.y;
                qA2 += va.z * va.z; qA3 += va.w * va.w;
                sB0 += vb.x; sB1 += vb.y; sB2 += vb.z; sB3 += vb.w;
                qB0 += vb.x * vb.x; qB1 += vb.y * vb.y;
                qB2 += vb.z * vb.z; qB3 += vb.w * vb.w;
            }
        } else if (n < nvb) {
            // Boundary slab: at most one per batch (<=16 total)
            int cnt = nvb - n;             // 1..3
            const float4* p = x + (size_t)row0 * ROW4;
            for (int r = 0; r < cnt; r++) {
                float4 va = p[r * ROW4 + lane];
                float4 vb = p[r * ROW4 + lane + 32];
                sA0 += va.x; sA1 += va.y; sA2 += va.z; sA3 += va.w;
                qA0 += va.x * va.x; qA1 += va.y * va.y;
                qA2 += va.z * va.z; qA3 += va.w * va.w;
                sB0 += vb.x; sB1 += vb.y; sB2 += vb.z; sB3 += vb.w;
                qB0 += vb.x * vb.x; qB1 += vb.y * vb.y;
                qB2 += vb.z * vb.z; qB3 += vb.w * vb.w;
            }
        }
        // else fully padded: skip
    }

    // Cross-warp reduction, conflict-free:
    //  - store: red[j*1024 + tid]  (stride-1, no conflicts)
    //  - read:  128 threads, l = f&31 (bank), j = f>>5; feature = 4*l + j
    __shared__ float red[4 * STATS_T];
    float* myPart = &g_part[(size_t)blockIdx.x * (2 * FF)];

    #define RED_ROUND(v0, v1, v2, v3, foff)                                    \
        red[0 * STATS_T + tid] = v0; red[1 * STATS_T + tid] = v1;              \
        red[2 * STATS_T + tid] = v2; red[3 * STATS_T + tid] = v3;              \
        __syncthreads();                                                       \
        if (tid < 128) {                                                       \
            int l = tid & 31, j = tid >> 5;                                    \
            float t = 0.f;                                                     \
            _Pragma("unroll")                                                  \
            for (int w = 0; w < 32; w++) t += red[j * STATS_T + w * 32 + l];   \
            myPart[(foff) + 4 * l + j] = t;                                    \
        }                                                                      \
        __syncthreads();

    RED_ROUND(sA0, sA1, sA2, sA3, 0)          // sum, features 0..127
    RED_ROUND(sB0, sB1, sB2, sB3, 128)        // sum, features 128..255
    RED_ROUND(qA0, qA1, qA2, qA3, 256)        // sumsq, features 0..127
    RED_ROUND(qB0, qB1, qB2, qB3, 256 + 128)  // sumsq, features 128..255
    #undef RED_ROUND
}

// ---------------- kernel 2: reduce partials + finalize scale/shift ----------------
// 1024 threads: chunk c = tid>>8 handles 37 of the 148 blocks for feature f = tid&255.
__global__ __launch_bounds__(1024, 1)
void mbn_finalize_kernel(const int* __restrict__ nv,
                         const float* __restrict__ gamma,
                         const float* __restrict__ beta) {
    __shared__ float s_sum[4][FF];
    __shared__ float s_sq[4][FF];
    __shared__ float s_cnt;
    int tid = threadIdx.x;
    if (tid == 0) {
        int c = 0;
        #pragma unroll
        for (int i = 0; i < BB; i++) c += nv[i];
        s_cnt = fmaxf((float)c, 1.0f);
    }

    int c = tid >> 8;            // 0..3
    int f = tid & 255;
    float sum = 0.f, sumsq = 0.f;
    int b0 = c * 37;             // 148 = 4 * 37
    #pragma unroll 8
    for (int i = 0; i < 37; i++) {
        const float* p = &g_part[(size_t)(b0 + i) * (2 * FF)];
        sum   += p[f];
        sumsq += p[FF + f];
    }
    s_sum[c][f] = sum;
    s_sq[c][f]  = sumsq;
    __syncthreads();

    if (tid < FF) {
        float S = s_sum[0][tid] + s_sum[1][tid] + s_sum[2][tid] + s_sum[3][tid];
        float Q = s_sq[0][tid]  + s_sq[1][tid]  + s_sq[2][tid]  + s_sq[3][tid];
        float cnt  = s_cnt;
        float mean = S / cnt;
        float var  = Q / cnt - mean * mean;
        float inv  = rsqrtf(var + EPS);
        float sc   = inv * gamma[tid];
        g_scale[tid] = sc;
        g_shift[tid] = beta[tid] - mean * sc;
    }
}

// ---------------- kernel 3: normalize + zero padding (warp-slab, grid-stride) ----------------
// Unchanged from R8/R9 (measured 29.3us, at the HBM wall).
__global__ void mbn_norm_kernel(const float4* __restrict__ x,
                                const int* __restrict__ nv,
                                float4* __restrict__ out) {
    __shared__ int s_nv[BB];
    if (threadIdx.x < BB) s_nv[threadIdx.x] = nv[threadIdx.x];
    __syncthreads();

    int tid  = threadIdx.x;
    int lane = tid & 31;
    int gw   = blockIdx.x * (blockDim.x >> 5) + (tid >> 5);
    int W    = gridDim.x * (blockDim.x >> 5);

    // Register-resident scale/shift: lane l only ever touches cols l and l+32.
    const float4* sc4 = (const float4*)g_scale;
    const float4* sh4 = (const float4*)g_shift;
    float4 scA = sc4[lane], scB = sc4[lane + 32];
    float4 shA = sh4[lane], shB = sh4[lane + 32];
    const float4 z4 = make_float4(0.f, 0.f, 0.f, 0.f);

    for (int s = gw; s < NSLAB; s += W) {
        int row0 = s << 2;
        int n    = row0 & (NN - 1);
        int b    = row0 >> 13;
        int nvb  = s_nv[b];
        size_t off = (size_t)row0 * ROW4;
        float4* po = out + off;

        if (n + SLAB_ROWS <= nvb) {
            const float4* p = x + off;
            #pragma unroll
            for (int r = 0; r < SLAB_ROWS; r++) {
                float4 va = p[r * ROW4 + lane];
                float4 vb = p[r * ROW4 + lane + 32];
                float4 ra, rb;
                ra.x = fmaf(va.x, scA.x, shA.x);
                ra.y = fmaf(va.y, scA.y, shA.y);
                ra.z = fmaf(va.z, scA.z, shA.z);
                ra.w = fmaf(va.w, scA.w, shA.w);
                rb.x = fmaf(vb.x, scB.x, shB.x);
                rb.y = fmaf(vb.y, scB.y, shB.y);
                rb.z = fmaf(vb.z, scB.z, shB.z);
                rb.w = fmaf(vb.w, scB.w, shB.w);
                po[r * ROW4 + lane]      = ra;
                po[r * ROW4 + lane + 32] = rb;
            }
        } else if (n >= nvb) {
            // Fully padded slab: store-only zero fill, no reads.
            #pragma unroll
            for (int r = 0; r < SLAB_ROWS; r++) {
                po[r * ROW4 + lane]      = z4;
                po[r * ROW4 + lane + 32] = z4;
            }
        } else {
            // Boundary slab (<=16 total)
            int cnt = nvb - n;             // 1..3
            const float4* p = x + off;
            #pragma unroll
            for (int r = 0; r < SLAB_ROWS; r++) {
                float4 ra = z4, rb = z4;
                if (r < cnt) {
                    float4 va = p[r * ROW4 + lane];
                    float4 vb = p[r * ROW4 + lane + 32];
                    ra.x = fmaf(va.x, scA.x, shA.x);
                    ra.y = fmaf(va.y, scA.y, shA.y);
                    ra.z = fmaf(va.z, scA.z, shA.z);
                    ra.w = fmaf(va.w, scA.w, shA.w);
                    rb.x = fmaf(vb.x, scB.x, shB.x);
                    rb.y = fmaf(vb.y, scB.y, shB.y);
                    rb.z = fmaf(vb.z, scB.z, shB.z);
                    rb.w = fmaf(vb.w, scB.w, shB.w);
                }
                po[r * ROW4 + lane]      = ra;
                po[r * ROW4 + lane + 32] = rb;
            }
        }
    }
}

extern "C" void kernel_launch(void* const* d_in, const int* in_sizes, int n_in,
                              void* d_out, int out_size) {
    const float4* x     = (const float4*)d_in[0];   // voxel_features [16,8192,256]
    const int*    nv    = (const int*)d_in[1];      // num_valid_voxels [16]
    const float*  gamma = (const float*)d_in[2];    // [256]
    const float*  beta  = (const float*)d_in[3];    // [256]
    float4*       out   = (float4*)d_out;

    mbn_stats_kernel<<<NBLK, STATS_T>>>(x, nv);          // 148 blocks x 1024 thr, no atomics
    mbn_finalize_kernel<<<1, 1024>>>(nv, gamma, beta);
    mbn_norm_kernel<<<148 * 8, 256>>>(x, nv, out);
}

// round 13
// speedup vs baseline: 1.8632x; 1.1275x over previous
#include <cuda_runtime.h>

// Problem shape (fixed by the dataset)
#define BB 16
#define NN 8192
#define FF 256
#define ROW4 64                       // float4s per row (FF/4)
#define NROWS (BB * NN)               // 131072
#define SLAB_ROWS 4
#define NSLAB (NROWS / SLAB_ROWS)     // 32768 warp-slabs
#define NBLK 148                      // one block per SM (wave-1 co-resident -> spin is safe)
#define NT 1024                       // 32 warps per block
#define EPS 1e-3f

// Scratch (allocation-free rule: __device__ globals)
__device__ __align__(16) float g_part[NBLK * 2 * FF];
__device__ __align__(16) float g_scale[FF];
__device__ __align__(16) float g_shift[FF];

// Reset-safe grid barrier state (returns to all-zero at the end of every launch,
// so graph replays see identical initial state).
__device__ int g_ctr0, g_flag0, g_ack0;
__device__ int g_ctr1, g_flag1, g_ack1;

// Called by tid 0 of every block. Counter -> flag -> ack; the 148th acker
// (which can only exist after ALL blocks observed the flag) resets the triple.
__device__ __forceinline__ void grid_bar(int* ctr, int* flag, int* ack) {
    __threadfence();                               // publish my stores (L2)
    int p = atomicAdd(ctr, 1);
    if (p == NBLK - 1) atomicExch(flag, 1);        // last arriver releases
    while (atomicAdd(flag, 0) == 0) __nanosleep(64);
    int a = atomicAdd(ack, 1);
    if (a == NBLK - 1) {                           // everyone has passed the spin
        *flag = 0; *ctr = 0; *ack = 0;
        __threadfence();
    }
}

__global__ __launch_bounds__(NT, 1)
void mbn_fused_kernel(const float4* __restrict__ x,
                      const int* __restrict__ nv,
                      const float* __restrict__ gamma,
                      const float* __restrict__ beta,
                      float4* __restrict__ out) {
    __shared__ int   s_nv[BB];
    __shared__ float s_buf[4 * NT];                // 16 KB: reduction scratch (A), combine (B)

    int tid  = threadIdx.x;
    int lane = tid & 31;
    int gw   = blockIdx.x * (NT >> 5) + (tid >> 5);
    const int W = NBLK * (NT >> 5);                // 4736 warps chip-wide

    if (tid < BB) s_nv[tid] = nv[tid];
    __syncthreads();

    // ================= Phase A: masked sum / sumsq =================
    {
        float sA0 = 0.f, sA1 = 0.f, sA2 = 0.f, sA3 = 0.f;
        float sB0 = 0.f, sB1 = 0.f, sB2 = 0.f, sB3 = 0.f;
        float qA0 = 0.f, qA1 = 0.f, qA2 = 0.f, qA3 = 0.f;
        float qB0 = 0.f, qB1 = 0.f, qB2 = 0.f, qB3 = 0.f;

        for (int s = gw; s < NSLAB; s += W) {
            int row0 = s << 2;
            int n    = row0 & (NN - 1);
            int b    = row0 >> 13;
            int nvb  = s_nv[b];
            if (n + SLAB_ROWS <= nvb) {
                const float4* p = x + (size_t)row0 * ROW4;
                float4 va[SLAB_ROWS], vb[SLAB_ROWS];
                #pragma unroll
                for (int r = 0; r < SLAB_ROWS; r++) {        // loads first (batched)
                    va[r] = p[r * ROW4 + lane];
                    vb[r] = p[r * ROW4 + lane + 32];
                }
                #pragma unroll
                for (int r = 0; r < SLAB_ROWS; r++) {        // then consume
                    sA0 += va[r].x; sA1 += va[r].y; sA2 += va[r].z; sA3 += va[r].w;
                    qA0 += va[r].x * va[r].x; qA1 += va[r].y * va[r].y;
                    qA2 += va[r].z * va[r].z; qA3 += va[r].w * va[r].w;
                    sB0 += vb[r].x; sB1 += vb[r].y; sB2 += vb[r].z; sB3 += vb[r].w;
                    qB0 += vb[r].x * vb[r].x; qB1 += vb[r].y * vb[r].y;
                    qB2 += vb[r].z * vb[r].z; qB3 += vb[r].w * vb[r].w;
                }
            } else if (n < nvb) {
                int cnt = nvb - n;                            // 1..3, <=16 slabs total
                const float4* p = x + (size_t)row0 * ROW4;
                for (int r = 0; r < cnt; r++) {
                    float4 va = p[r * ROW4 + lane];
                    float4 vb = p[r * ROW4 + lane + 32];
                    sA0 += va.x; sA1 += va.y; sA2 += va.z; sA3 += va.w;
                    qA0 += va.x * va.x; qA1 += va.y * va.y;
                    qA2 += va.z * va.z; qA3 += va.w * va.w;
                    sB0 += vb.x; sB1 += vb.y; sB2 += vb.z; sB3 += vb.w;
                    qB0 += vb.x * vb.x; qB1 += vb.y * vb.y;
                    qB2 += vb.z * vb.z; qB3 += vb.w * vb.w;
                }
            }
        }

        // Conflict-free cross-warp reduction, then STORE partials (no atomics).
        float* myPart = &g_part[(size_t)blockIdx.x * (2 * FF)];
        #define RED_ROUND(v0, v1, v2, v3, foff)                                  \
            s_buf[0 * NT + tid] = v0; s_buf[1 * NT + tid] = v1;                  \
            s_buf[2 * NT + tid] = v2; s_buf[3 * NT + tid] = v3;                  \
            __syncthreads();                                                     \
            if (tid < 128) {                                                     \
                int l = tid & 31, j = tid >> 5;                                  \
                float t = 0.f;                                                   \
                _Pragma("unroll")                                                \
                for (int w = 0; w < 32; w++) t += s_buf[j * NT + w * 32 + l];    \
                myPart[(foff) + 4 * l + j] = t;                                  \
            }                                                                    \
            __syncthreads();

        RED_ROUND(sA0, sA1, sA2, sA3, 0)
        RED_ROUND(sB0, sB1, sB2, sB3, 128)
        RED_ROUND(qA0, qA1, qA2, qA3, 256)
        RED_ROUND(qB0, qB1, qB2, qB3, 256 + 128)
        #undef RED_ROUND
    }

    // ================= Barrier 0: all partials published =================
    if (tid == 0) grid_bar(&g_ctr0, &g_flag0, &g_ack0);
    __syncthreads();

    // ================= Phase B: block 0 reduces partials + finalize =================
    if (blockIdx.x == 0) {
        __threadfence();                           // invalidate L1, read fresh partials
        float* s_sum = s_buf;                      // [4][FF]
        float* s_sq  = s_buf + 4 * FF;             // [4][FF]
        int c = tid >> 8;                          // 0..3
        int f = tid & 255;
        float sum = 0.f, sumsq = 0.f;
        int b0 = c * 37;                           // 148 = 4 * 37
        #pragma unroll 8
        for (int i = 0; i < 37; i++) {
            const float* p = &g_part[(size_t)(b0 + i) * (2 * FF)];
            sum   += p[f];
            sumsq += p[FF + f];
        }
        s_sum[c * FF + f] = sum;
        s_sq[c * FF + f]  = sumsq;
        __syncthreads();
        if (tid < FF) {
            int cn = 0;
            #pragma unroll
            for (int i = 0; i < BB; i++) cn += s_nv[i];
            float cnt  = fmaxf((float)cn, 1.0f);
            float S = s_sum[0 * FF + tid] + s_sum[1 * FF + tid] +
                      s_sum[2 * FF + tid] + s_sum[3 * FF + tid];
            float Q = s_sq[0 * FF + tid] + s_sq[1 * FF + tid] +
                      s_sq[2 * FF + tid] + s_sq[3 * FF + tid];
            float mean = S / cnt;
            float var  = Q / cnt - mean * mean;
            float inv  = rsqrtf(var + EPS);
            float sc   = inv * gamma[tid];
            g_scale[tid] = sc;
            g_shift[tid] = beta[tid] - mean * sc;
        }
        __syncthreads();
    }

    // ================= Barrier 1: scale/shift published =================
    if (tid == 0) grid_bar(&g_ctr1, &g_flag1, &g_ack1);
    __syncthreads();
    __threadfence();                               // all threads: flush L1 before reading g_scale

    // ================= Phase C: normalize + zero padding =================
    {
        const float4* sc4 = (const float4*)g_scale;
        const float4* sh4 = (const float4*)g_shift;
        float4 scA = sc4[lane], scB = sc4[lane + 32];
        float4 shA = sh4[lane], shB = sh4[lane + 32];
        const float4 z4 = make_float4(0.f, 0.f, 0.f, 0.f);

        for (int s = gw; s < NSLAB; s += W) {
            int row0 = s << 2;
            int n    = row0 & (NN - 1);
            int b    = row0 >> 13;
            int nvb  = s_nv[b];
            size_t off = (size_t)row0 * ROW4;
            float4* po = out + off;

            if (n + SLAB_ROWS <= nvb) {
                const float4* p = x + off;
                #pragma unroll
                for (int r = 0; r < SLAB_ROWS; r++) {
                    float4 va = p[r * ROW4 + lane];
                    float4 vb = p[r * ROW4 + lane + 32];
                    float4 ra, rb;
                    ra.x = fmaf(va.x, scA.x, shA.x);
                    ra.y = fmaf(va.y, scA.y, shA.y);
                    ra.z = fmaf(va.z, scA.z, shA.z);
                    ra.w = fmaf(va.w, scA.w, shA.w);
                    rb.x = fmaf(vb.x, scB.x, shB.x);
                    rb.y = fmaf(vb.y, scB.y, shB.y);
                    rb.z = fmaf(vb.z, scB.z, shB.z);
                    rb.w = fmaf(vb.w, scB.w, shB.w);
                    po[r * ROW4 + lane]      = ra;
                    po[r * ROW4 + lane + 32] = rb;
                }
            } else if (n >= nvb) {
                #pragma unroll
                for (int r = 0; r < SLAB_ROWS; r++) {
                    po[r * ROW4 + lane]      = z4;
                    po[r * ROW4 + lane + 32] = z4;
                }
            } else {
                int cnt = nvb - n;                 // 1..3
                const float4* p = x + off;
                #pragma unroll
                for (int r = 0; r < SLAB_ROWS; r++) {
                    float4 ra = z4, rb = z4;
                    if (r < cnt) {
                        float4 va = p[r * ROW4 + lane];
                        float4 vb = p[r * ROW4 + lane + 32];
                        ra.x = fmaf(va.x, scA.x, shA.x);
                        ra.y = fmaf(va.y, scA.y, shA.y);
                        ra.z = fmaf(va.z, scA.z, shA.z);
                        ra.w = fmaf(va.w, scA.w, shA.w);
                        rb.x = fmaf(vb.x, scB.x, shB.x);
                        rb.y = fmaf(vb.y, scB.y, shB.y);
                        rb.z = fmaf(vb.z, scB.z, shB.z);
                        rb.w = fmaf(vb.w, scB.w, shB.w);
                    }
                    po[r * ROW4 + lane]      = ra;
                    po[r * ROW4 + lane + 32] = rb;
                }
            }
        }
    }
}

extern "C" void kernel_launch(void* const* d_in, const int* in_sizes, int n_in,
                              void* d_out, int out_size) {
    const float4* x     = (const float4*)d_in[0];   // voxel_features [16,8192,256]
    const int*    nv    = (const int*)d_in[1];      // num_valid_voxels [16]
    const float*  gamma = (const float*)d_in[2];    // [256]
    const float*  beta  = (const float*)d_in[3];    // [256]
    float4*       out   = (float4*)d_out;

    mbn_fused_kernel<<<NBLK, NT>>>(x, nv, gamma, beta, out);
}

// round 14
// speedup vs baseline: 1.9401x; 1.0412x over previous
#include <cuda_runtime.h>

// Problem shape (fixed by the dataset)
#define BB 16
#define NN 8192
#define FF 256
#define ROW4 64                       // float4s per row (FF/4)
#define NROWS (BB * NN)               // 131072
#define SLAB_ROWS 4
#define NSLAB (NROWS / SLAB_ROWS)     // 32768 warp-slabs
#define NBLK 148                      // one block per SM (wave-1 co-resident -> spin is safe)
#define NT 1024                       // 32 warps per block
#define EPS 1e-3f

// Scratch (allocation-free rule: __device__ globals)
__device__ __align__(16) float g_part[NBLK * 2 * FF];
__device__ __align__(16) float g_scale[FF];
__device__ __align__(16) float g_shift[FF];

// Reset-safe grid barrier state (returns to all-zero at the end of every launch,
// so graph replays see identical initial state).
__device__ int g_ctr0, g_flag0, g_ack0;
__device__ int g_ctr1, g_flag1, g_ack1;

// Called by tid 0 of every block. Counter -> flag -> ack; the 148th acker
// (which can only exist after ALL blocks observed the flag) resets the triple.
__device__ __forceinline__ void grid_bar(int* ctr, int* flag, int* ack) {
    __threadfence();                               // publish my stores (L2)
    int p = atomicAdd(ctr, 1);
    if (p == NBLK - 1) atomicExch(flag, 1);        // last arriver releases
    while (atomicAdd(flag, 0) == 0) __nanosleep(64);
    int a = atomicAdd(ack, 1);
    if (a == NBLK - 1) {                           // everyone has passed the spin
        *flag = 0; *ctr = 0; *ack = 0;
        __threadfence();
    }
}

__global__ __launch_bounds__(NT, 1)
void mbn_fused_kernel(const float4* __restrict__ x,
                      const int* __restrict__ nv,
                      const float* __restrict__ gamma,
                      const float* __restrict__ beta,
                      float4* __restrict__ out) {
    __shared__ int   s_nv[BB];
    __shared__ float s_buf[4 * NT];                // 16 KB: reduction scratch (A), combine (B)

    int tid  = threadIdx.x;
    int lane = tid & 31;
    int gw   = blockIdx.x * (NT >> 5) + (tid >> 5);
    const int W = NBLK * (NT >> 5);                // 4736 warps chip-wide

    if (tid < BB) s_nv[tid] = nv[tid];
    __syncthreads();

    // ================= Phase A: masked sum / sumsq =================
    // Loads use __ldcg: L2-only fill (installs x in L2 for phase C, no L1 thrash).
    {
        float sA0 = 0.f, sA1 = 0.f, sA2 = 0.f, sA3 = 0.f;
        float sB0 = 0.f, sB1 = 0.f, sB2 = 0.f, sB3 = 0.f;
        float qA0 = 0.f, qA1 = 0.f, qA2 = 0.f, qA3 = 0.f;
        float qB0 = 0.f, qB1 = 0.f, qB2 = 0.f, qB3 = 0.f;

        for (int s = gw; s < NSLAB; s += W) {
            int row0 = s << 2;
            int n    = row0 & (NN - 1);
            int b    = row0 >> 13;
            int nvb  = s_nv[b];
            if (n + SLAB_ROWS <= nvb) {
                const float4* p = x + (size_t)row0 * ROW4;
                float4 va[SLAB_ROWS], vb[SLAB_ROWS];
                #pragma unroll
                for (int r = 0; r < SLAB_ROWS; r++) {        // loads first (batched)
                    va[r] = __ldcg(&p[r * ROW4 + lane]);
                    vb[r] = __ldcg(&p[r * ROW4 + lane + 32]);
                }
                #pragma unroll
                for (int r = 0; r < SLAB_ROWS; r++) {        // then consume
                    sA0 += va[r].x; sA1 += va[r].y; sA2 += va[r].z; sA3 += va[r].w;
                    qA0 += va[r].x * va[r].x; qA1 += va[r].y * va[r].y;
                    qA2 += va[r].z * va[r].z; qA3 += va[r].w * va[r].w;
                    sB0 += vb[r].x; sB1 += vb[r].y; sB2 += vb[r].z; sB3 += vb[r].w;
                    qB0 += vb[r].x * vb[r].x; qB1 += vb[r].y * vb[r].y;
                    qB2 += vb[r].z * vb[r].z; qB3 += vb[r].w * vb[r].w;
                }
            } else if (n < nvb) {
                int cnt = nvb - n;                            // 1..3, <=16 slabs total
                const float4* p = x + (size_t)row0 * ROW4;
                for (int r = 0; r < cnt; r++) {
                    float4 va = __ldcg(&p[r * ROW4 + lane]);
                    float4 vb = __ldcg(&p[r * ROW4 + lane + 32]);
                    sA0 += va.x; sA1 += va.y; sA2 += va.z; sA3 += va.w;
                    qA0 += va.x * va.x; qA1 += va.y * va.y;
                    qA2 += va.z * va.z; qA3 += va.w * va.w;
                    sB0 += vb.x; sB1 += vb.y; sB2 += vb.z; sB3 += vb.w;
                    qB0 += vb.x * vb.x; qB1 += vb.y * vb.y;
                    qB2 += vb.z * vb.z; qB3 += vb.w * vb.w;
                }
            }
        }

        // Conflict-free cross-warp reduction, then STORE partials (no atomics).
        float* myPart = &g_part[(size_t)blockIdx.x * (2 * FF)];
        #define RED_ROUND(v0, v1, v2, v3, foff)                                  \
            s_buf[0 * NT + tid] = v0; s_buf[1 * NT + tid] = v1;                  \
            s_buf[2 * NT + tid] = v2; s_buf[3 * NT + tid] = v3;                  \
            __syncthreads();                                                     \
            if (tid < 128) {                                                     \
                int l = tid & 31, j = tid >> 5;                                  \
                float t = 0.f;                                                   \
                _Pragma("unroll")                                                \
                for (int w = 0; w < 32; w++) t += s_buf[j * NT + w * 32 + l];    \
                myPart[(foff) + 4 * l + j] = t;                                  \
            }                                                                    \
            __syncthreads();

        RED_ROUND(sA0, sA1, sA2, sA3, 0)
        RED_ROUND(sB0, sB1, sB2, sB3, 128)
        RED_ROUND(qA0, qA1, qA2, qA3, 256)
        RED_ROUND(qB0, qB1, qB2, qB3, 256 + 128)
        #undef RED_ROUND
    }

    // ================= Barrier 0: all partials published =================
    if (tid == 0) grid_bar(&g_ctr0, &g_flag0, &g_ack0);
    __syncthreads();

    // ================= Phase B: block 0 reduces partials + finalize =================
    if (blockIdx.x == 0) {
        __threadfence();                           // invalidate L1, read fresh partials
        float* s_sum = s_buf;                      // [4][FF]
        float* s_sq  = s_buf + 4 * FF;             // [4][FF]
        int c = tid >> 8;                          // 0..3
        int f = tid & 255;
        float sum = 0.f, sumsq = 0.f;
        int b0 = c * 37;                           // 148 = 4 * 37
        #pragma unroll 8
        for (int i = 0; i < 37; i++) {
            const float* p = &g_part[(size_t)(b0 + i) * (2 * FF)];
            sum   += __ldcg(&p[f]);
            sumsq += __ldcg(&p[FF + f]);
        }
        s_sum[c * FF + f] = sum;
        s_sq[c * FF + f]  = sumsq;
        __syncthreads();
        if (tid < FF) {
            int cn = 0;
            #pragma unroll
            for (int i = 0; i < BB; i++) cn += s_nv[i];
            float cnt  = fmaxf((float)cn, 1.0f);
            float S = s_sum[0 * FF + tid] + s_sum[1 * FF + tid] +
                      s_sum[2 * FF + tid] + s_sum[3 * FF + tid];
            float Q = s_sq[0 * FF + tid] + s_sq[1 * FF + tid] +
                      s_sq[2 * FF + tid] + s_sq[3 * FF + tid];
            float mean = S / cnt;
            float var  = Q / cnt - mean * mean;
            float inv  = rsqrtf(var + EPS);
            float sc   = inv * gamma[tid];
            g_scale[tid] = sc;
            g_shift[tid] = beta[tid] - mean * sc;
        }
        __syncthreads();
    }

    // ================= Barrier 1: scale/shift published =================
    if (tid == 0) grid_bar(&g_ctr1, &g_flag1, &g_ack1);
    __syncthreads();
    __threadfence();                               // all threads: flush L1 before reading g_scale

    // ================= Phase C: normalize + zero padding =================
    // Loads default (hit L2-resident x); stores __stcs (evict-first: the output
    // is never re-read, so keep the 128 MiB write stream from evicting x).
    {
        const float4* sc4 = (const float4*)g_scale;
        const float4* sh4 = (const float4*)g_shift;
        float4 scA = sc4[lane], scB = sc4[lane + 32];
        float4 shA = sh4[lane], shB = sh4[lane + 32];
        const float4 z4 = make_float4(0.f, 0.f, 0.f, 0.f);

        for (int s = gw; s < NSLAB; s += W) {
            int row0 = s << 2;
            int n    = row0 & (NN - 1);
            int b    = row0 >> 13;
            int nvb  = s_nv[b];
            size_t off = (size_t)row0 * ROW4;
            float4* po = out + off;

            if (n + SLAB_ROWS <= nvb) {
                const float4* p = x + off;
                #pragma unroll
                for (int r = 0; r < SLAB_ROWS; r++) {
                    float4 va = p[r * ROW4 + lane];
                    float4 vb = p[r * ROW4 + lane + 32];
                    float4 ra, rb;
                    ra.x = fmaf(va.x, scA.x, shA.x);
                    ra.y = fmaf(va.y, scA.y, shA.y);
                    ra.z = fmaf(va.z, scA.z, shA.z);
                    ra.w = fmaf(va.w, scA.w, shA.w);
                    rb.x = fmaf(vb.x, scB.x, shB.x);
                    rb.y = fmaf(vb.y, scB.y, shB.y);
                    rb.z = fmaf(vb.z, scB.z, shB.z);
                    rb.w = fmaf(vb.w, scB.w, shB.w);
                    __stcs(&po[r * ROW4 + lane],      ra);
                    __stcs(&po[r * ROW4 + lane + 32], rb);
                }
            } else if (n >= nvb) {
                #pragma unroll
                for (int r = 0; r < SLAB_ROWS; r++) {
                    __stcs(&po[r * ROW4 + lane],      z4);
                    __stcs(&po[r * ROW4 + lane + 32], z4);
                }
            } else {
                int cnt = nvb - n;                 // 1..3
                const float4* p = x + off;
                #pragma unroll
                for (int r = 0; r < SLAB_ROWS; r++) {
                    float4 ra = z4, rb = z4;
                    if (r < cnt) {
                        float4 va = p[r * ROW4 + lane];
                        float4 vb = p[r * ROW4 + lane + 32];
                        ra.x = fmaf(va.x, scA.x, shA.x);
                        ra.y = fmaf(va.y, scA.y, shA.y);
                        ra.z = fmaf(va.z, scA.z, shA.z);
                        ra.w = fmaf(va.w, scA.w, shA.w);
                        rb.x = fmaf(vb.x, scB.x, shB.x);
                        rb.y = fmaf(vb.y, scB.y, shB.y);
                        rb.z = fmaf(vb.z, scB.z, shB.z);
                        rb.w = fmaf(vb.w, scB.w, shB.w);
                    }
                    __stcs(&po[r * ROW4 + lane],      ra);
                    __stcs(&po[r * ROW4 + lane + 32], rb);
                }
            }
        }
    }
}

extern "C" void kernel_launch(void* const* d_in, const int* in_sizes, int n_in,
                              void* d_out, int out_size) {
    const float4* x     = (const float4*)d_in[0];   // voxel_features [16,8192,256]
    const int*    nv    = (const int*)d_in[1];      // num_valid_voxels [16]
    const float*  gamma = (const float*)d_in[2];    // [256]
    const float*  beta  = (const float*)d_in[3];    // [256]
    float4*       out   = (float4*)d_out;

    mbn_fused_kernel<<<NBLK, NT>>>(x, nv, gamma, beta, out);
}

// round 16
// speedup vs baseline: 2.0235x; 1.0430x over previous
#include <cuda_runtime.h>

// Problem shape (fixed by the dataset)
#define BB 16
#define NN 8192
#define FF 256
#define ROW4 64                       // float4s per row (FF/4)
#define NROWS (BB * NN)               // 131072
#define SLAB8 8                       // rows per work-unit slab
#define NSLAB8 (NROWS / SLAB8)        // 16384 slabs
#define NUNIT (NSLAB8 * 2)            // 32768 (slab, half) units
#define NBLK 148                      // one block per SM (wave-1 co-resident -> spin is safe)
#define NT 1024                       // 32 warps per block
#define EPS 1e-3f

// Scratch (allocation-free rule: __device__ globals)
__device__ __align__(16) float g_part[NBLK * 2 * FF];
__device__ __align__(16) float g_scale[FF];
__device__ __align__(16) float g_shift[FF];

// Reset-safe grid barrier state (returns to all-zero at the end of every launch,
// so graph replays see identical initial state).
__device__ int g_ctr0, g_flag0, g_ack0;
__device__ int g_ctr1, g_flag1, g_ack1;

__device__ __forceinline__ void grid_bar(int* ctr, int* flag, int* ack) {
    __threadfence();                               // publish my stores (L2)
    int p = atomicAdd(ctr, 1);
    if (p == NBLK - 1) atomicExch(flag, 1);        // last arriver releases
    while (atomicAdd(flag, 0) == 0) __nanosleep(64);
    int a = atomicAdd(ack, 1);
    if (a == NBLK - 1) {                           // everyone has passed the spin
        *flag = 0; *ctr = 0; *ack = 0;
        __threadfence();
    }
}

__global__ __launch_bounds__(NT, 1)
void mbn_fused_kernel(const float4* __restrict__ x,
                      const int* __restrict__ nv,
                      const float* __restrict__ gamma,
                      const float* __restrict__ beta,
                      float4* __restrict__ out) {
    __shared__ int   s_nv[BB];
    __shared__ float s_buf[4 * NT];                // 16 KB: reduction scratch (A), combine (B)

    int tid  = threadIdx.x;
    int lane = tid & 31;
    int gw   = blockIdx.x * (NT >> 5) + (tid >> 5);
    const int W = NBLK * (NT >> 5);                // 4736 warps chip-wide (even)
    const int h = gw & 1;                          // fixed half per warp (W even)
    const int colo = h * 32 + lane;                // my float4 column, fixed forever
    // My features: f(j) = h*128 + 4*lane + j, j=0..3

    if (tid < BB) s_nv[tid] = nv[tid];
    __syncthreads();

    // ================= Phase A: masked sum / sumsq =================
    // Work unit u = (slab s = u>>1 of 8 rows, half h = u&1). 8 accumulators/thread,
    // 8 unconditional batched __ldcg LDG.128 per valid unit (true MLP 8).
    {
        float s0 = 0.f, s1 = 0.f, s2 = 0.f, s3 = 0.f;
        float q0 = 0.f, q1 = 0.f, q2 = 0.f, q3 = 0.f;

        for (int u = gw; u < NUNIT; u += W) {
            int s    = u >> 1;
            int row0 = s << 3;                    // * SLAB8
            int n    = row0 & (NN - 1);
            int b    = row0 >> 13;
            int nvb  = s_nv[b];
            const float4* p = x + (size_t)row0 * ROW4 + colo;
            if (n + SLAB8 <= nvb) {
                float4 v[SLAB8];
                #pragma unroll
                for (int r = 0; r < SLAB8; r++)   // loads first (batched)
                    v[r] = __ldcg(p + r * ROW4);
                #pragma unroll
                for (int r = 0; r < SLAB8; r++) { // then consume
                    s0 += v[r].x; s1 += v[r].y; s2 += v[r].z; s3 += v[r].w;
                    q0 += v[r].x * v[r].x; q1 += v[r].y * v[r].y;
                    q2 += v[r].z * v[r].z; q3 += v[r].w * v[r].w;
                }
            } else if (n < nvb) {
                int cnt = nvb - n;                // 1..7, <=32 boundary units total
                for (int r = 0; r < cnt; r++) {
                    float4 v = __ldcg(p + r * ROW4);
                    s0 += v.x; s1 += v.y; s2 += v.z; s3 += v.w;
                    q0 += v.x * v.x; q1 += v.y * v.y;
                    q2 += v.z * v.z; q3 += v.w * v.w;
                }
            }
            // else fully padded: skip
        }

        // Cross-warp reduction (2 rounds). Thread holds feature h*128+4*lane+j
        // for component j. Reducers: l=tid&31 (bank), rest=tid>>5: j=rest&3, hh=rest>>2.
        // Sources (2w+hh)*32+l are bank-distinct in l -> conflict-free.
        float* myPart = &g_part[(size_t)blockIdx.x * (2 * FF)];
        #define RED_ROUND(v0, v1, v2, v3, foff)                                   \
            s_buf[0 * NT + tid] = v0; s_buf[1 * NT + tid] = v1;                   \
            s_buf[2 * NT + tid] = v2; s_buf[3 * NT + tid] = v3;                   \
            __syncthreads();                                                      \
            if (tid < 256) {                                                      \
                int l = tid & 31, rest = tid >> 5;                                \
                int j = rest & 3, hh = rest >> 2;                                 \
                float t = 0.f;                                                    \
                _Pragma("unroll")                                                 \
                for (int w = 0; w < 16; w++)                                      \
                    t += s_buf[j * NT + (2 * w + hh) * 32 + l];                   \
                myPart[(foff) + hh * 128 + 4 * l + j] = t;                        \
            }                                                                     \
            __syncthreads();

        RED_ROUND(s0, s1, s2, s3, 0)              // sums, features 0..255
        RED_ROUND(q0, q1, q2, q3, FF)             // sumsqs
        #undef RED_ROUND
    }

    // ================= Barrier 0: all partials published =================
    if (tid == 0) grid_bar(&g_ctr0, &g_flag0, &g_ack0);
    __syncthreads();

    // ================= Phase B: block 0 reduces partials + finalize =================
    if (blockIdx.x == 0) {
        __threadfence();
        float* s_sum = s_buf;                      // [4][FF]
        float* s_sq  = s_buf + 4 * FF;             // [4][FF]
        int c = tid >> 8;                          // 0..3
        int f = tid & 255;
        float sum = 0.f, sumsq = 0.f;
        int b0 = c * 37;                           // 148 = 4 * 37
        #pragma unroll 8
        for (int i = 0; i < 37; i++) {
            const float* p = &g_part[(size_t)(b0 + i) * (2 * FF)];
            sum   += __ldcg(&p[f]);
            sumsq += __ldcg(&p[FF + f]);
        }
        s_sum[c * FF + f] = sum;
        s_sq[c * FF + f]  = sumsq;
        __syncthreads();
        if (tid < FF) {
            int cn = 0;
            #pragma unroll
            for (int i = 0; i < BB; i++) cn += s_nv[i];
            float cnt  = fmaxf((float)cn, 1.0f);
            float S = s_sum[0 * FF + tid] + s_sum[1 * FF + tid] +
                      s_sum[2 * FF + tid] + s_sum[3 * FF + tid];
            float Q = s_sq[0 * FF + tid] + s_sq[1 * FF + tid] +
                      s_sq[2 * FF + tid] + s_sq[3 * FF + tid];
            float mean = S / cnt;
            float var  = Q / cnt - mean * mean;
            float inv  = rsqrtf(var + EPS);
            float sc   = inv * gamma[tid];
            g_scale[tid] = sc;
            g_shift[tid] = beta[tid] - mean * sc;
        }
        __syncthreads();
    }

    // ================= Barrier 1: scale/shift published =================
    if (tid == 0) grid_bar(&g_ctr1, &g_flag1, &g_ack1);
    __syncthreads();
    __threadfence();                               // flush L1 before reading g_scale

    // ================= Phase C: normalize + zero padding =================
    // Same (slab, half) units; only ONE float4 scale/shift pair per thread.
    // Loads default (hit L2-resident x); stores __stcs (evict-first).
    {
        const float4 sc = ((const float4*)g_scale)[colo];
        const float4 sh = ((const float4*)g_shift)[colo];
        const float4 z4 = make_float4(0.f, 0.f, 0.f, 0.f);

        for (int u = gw; u < NUNIT; u += W) {
            int s    = u >> 1;
            int row0 = s << 3;
            int n    = row0 & (NN - 1);
            int b    = row0 >> 13;
            int nvb  = s_nv[b];
            size_t off = (size_t)row0 * ROW4 + colo;
            const float4* p  = x + off;
            float4*       po = out + off;

            if (n + SLAB8 <= nvb) {
                float4 v[SLAB8];
                #pragma unroll
                for (int r = 0; r < SLAB8; r++)   // batched loads
                    v[r] = p[r * ROW4];
                #pragma unroll
                for (int r = 0; r < SLAB8; r++) {
                    float4 ra;
                    ra.x = fmaf(v[r].x, sc.x, sh.x);
                    ra.y = fmaf(v[r].y, sc.y, sh.y);
                    ra.z = fmaf(v[r].z, sc.z, sh.z);
                    ra.w = fmaf(v[r].w, sc.w, sh.w);
                    __stcs(po + r * ROW4, ra);
                }
            } else if (n >= nvb) {
                #pragma unroll
                for (int r = 0; r < SLAB8; r++)
                    __stcs(po + r * ROW4, z4);
            } else {
                int cnt = nvb - n;                // 1..7
                #pragma unroll
                for (int r = 0; r < SLAB8; r++) {
                    float4 ra = z4;
                    if (r < cnt) {
                        float4 v = p[r * ROW4];
                        ra.x = fmaf(v.x, sc.x, sh.x);
                        ra.y = fmaf(v.y, sc.y, sh.y);
                        ra.z = fmaf(v.z, sc.z, sh.z);
                        ra.w = fmaf(v.w, sc.w, sh.w);
                    }
                    __stcs(po + r * ROW4, ra);
                }
            }
        }
    }
}

extern "C" void kernel_launch(void* const* d_in, const int* in_sizes, int n_in,
                              void* d_out, int out_size) {
    const float4* x     = (const float4*)d_in[0];   // voxel_features [16,8192,256]
    const int*    nv    = (const int*)d_in[1];      // num_valid_voxels [16]
    const float*  gamma = (const float*)d_in[2];    // [256]
    const float*  beta  = (const float*)d_in[3];    // [256]
    float4*       out   = (float4*)d_out;

    mbn_fused_kernel<<<NBLK, NT>>>(x, nv, gamma, beta, out);
}